// round 8
// baseline (speedup 1.0000x reference)
#include <cuda_runtime.h>

// DCN CrossLayer closed form: out = x0 * a3 + (b0+b1+b2), with
//   d_l = dot(x0, w_l), c1 = dot(b0,w1), c2 = dot(b0+b1,w2),
//   a1 = 1+d0; s1 = a1*d1+c1; a2 = a1+s1; s2 = a2*d2+c2; a3 = a2+s2.
//
// Warp-per-row: after a one-sync block prologue (c1,c2 scalars + B staged in
// smem), each warp handles one row with ZERO synchronization: 8 LDG.128,
// one fused pass computing all 3 dots (w streamed through L1, hot),
// a 9-SHFL batched butterfly, and the fused epilogue.

#define F_DIM 1024
#define F4    256
#define FULL  0xffffffffu

__device__ __forceinline__ float dot4(float4 a, float4 b, float acc) {
    acc = fmaf(a.x, b.x, acc);
    acc = fmaf(a.y, b.y, acc);
    acc = fmaf(a.z, b.z, acc);
    return fmaf(a.w, b.w, acc);
}

// Pairing step: merges two independent reductions one level deeper.
// Lanes with (lane&off)==0 accumulate 'a', others accumulate 'b'.
__device__ __forceinline__ float pair_step(float a, float b, int off, int lane) {
    const bool hi = (lane & off) != 0;
    float keep = hi ? b : a;
    float send = hi ? a : b;
    return keep + __shfl_xor_sync(FULL, send, off);
}

__global__ void __launch_bounds__(256, 4)
cross_layer_kernel(const float4* __restrict__ x,
                   const float*  __restrict__ w,   // [3,1024]
                   const float*  __restrict__ b,   // [3,1024]
                   float4* __restrict__ out)
{
    __shared__ float4 sB[F4];     // b0+b1+b2 per feature chunk
    __shared__ float2 sC[8];      // (c1,c2) warp partials

    const int tid  = threadIdx.x;
    const int lane = tid & 31;
    const int wid  = tid >> 5;

    // ---- Prologue: B into smem, c1/c2 block scalars. ONE sync. ----
    {
        const float4 w1v = __ldg(&((const float4*)(w + F_DIM))[tid]);
        const float4 w2v = __ldg(&((const float4*)(w + 2 * F_DIM))[tid]);
        const float4 b0v = __ldg(&((const float4*)(b))[tid]);
        const float4 b1v = __ldg(&((const float4*)(b + F_DIM))[tid]);
        const float4 b2v = __ldg(&((const float4*)(b + 2 * F_DIM))[tid]);

        float4 b01, B;
        b01.x = b0v.x + b1v.x;  b01.y = b0v.y + b1v.y;
        b01.z = b0v.z + b1v.z;  b01.w = b0v.w + b1v.w;
        B.x = b01.x + b2v.x;    B.y = b01.y + b2v.y;
        B.z = b01.z + b2v.z;    B.w = b01.w + b2v.w;
        sB[tid] = B;

        // Batched 2-scalar butterfly: c1 partial -> lane 0, c2 -> lane 16.
        float q = pair_step(dot4(b0v, w1v, 0.0f), dot4(b01, w2v, 0.0f), 16, lane);
#pragma unroll
        for (int o = 8; o; o >>= 1) q += __shfl_xor_sync(FULL, q, o);
        if (lane == 0)  sC[wid].x = q;
        if (lane == 16) sC[wid].y = q;
    }
    __syncthreads();

    float c1 = 0.0f, c2 = 0.0f;
#pragma unroll
    for (int i = 0; i < 8; i++) { float2 v = sC[i]; c1 += v.x; c2 += v.y; }

    // ---- Warp-per-row main path: no further synchronization. ----
    const int row = blockIdx.x * 8 + wid;
    const float4* __restrict__ xrow = x + (size_t)row * F4;
    float4*       __restrict__ orow = out + (size_t)row * F4;

    // Front-batched coalesced x loads.
    float4 x0[8];
#pragma unroll
    for (int i = 0; i < 8; i++)
        x0[i] = __ldg(&xrow[i * 32 + lane]);

    // Fused pass: all three dots (w streamed, L1-resident after first row).
    const float4* __restrict__ w0g = (const float4*)(w);
    const float4* __restrict__ w1g = (const float4*)(w + F_DIM);
    const float4* __restrict__ w2g = (const float4*)(w + 2 * F_DIM);

    float p0 = 0.0f, p1 = 0.0f, p2 = 0.0f;
#pragma unroll
    for (int i = 0; i < 8; i++) {
        const int idx = i * 32 + lane;
        p0 = dot4(x0[i], __ldg(&w0g[idx]), p0);
        p1 = dot4(x0[i], __ldg(&w1g[idx]), p1);
        p2 = dot4(x0[i], __ldg(&w2g[idx]), p2);
    }

    // Batched 3-scalar butterfly (6 SHFL) + 3 broadcasts.
    // Tree: pair(p0,p1) on bit4; p2 self-reduced on bit4; pair on bit3;
    // xor-reduce bits 2..0.  Result: lane0=d0, lane16=d1, lane8=d2.
    float t01 = pair_step(p0, p1, 16, lane);
    float t2  = p2 + __shfl_xor_sync(FULL, p2, 16);
    float q   = pair_step(t01, t2, 8, lane);
    q += __shfl_xor_sync(FULL, q, 4);
    q += __shfl_xor_sync(FULL, q, 2);
    q += __shfl_xor_sync(FULL, q, 1);

    const float d0 = __shfl_sync(FULL, q, 0);
    const float d1 = __shfl_sync(FULL, q, 16);
    const float d2 = __shfl_sync(FULL, q, 8);

    const float a1 = 1.0f + d0;
    const float s1 = fmaf(a1, d1, c1);
    const float a2 = a1 + s1;
    const float s2 = fmaf(a2, d2, c2);
    const float a3 = a2 + s2;

    // Epilogue: out = x0 * a3 + B (B from smem, conflict-free).
#pragma unroll
    for (int i = 0; i < 8; i++) {
        const int idx = i * 32 + lane;
        const float4 Bv = sB[idx];
        float4 o;
        o.x = fmaf(x0[i].x, a3, Bv.x);
        o.y = fmaf(x0[i].y, a3, Bv.y);
        o.z = fmaf(x0[i].z, a3, Bv.z);
        o.w = fmaf(x0[i].w, a3, Bv.w);
        orow[idx] = o;
    }
}

extern "C" void kernel_launch(void* const* d_in, const int* in_sizes, int n_in,
                              void* d_out, int out_size)
{
    const float4* x = (const float4*)d_in[0];
    const float*  w = (const float*)d_in[1];   // [3,1024,1]
    const float*  b = (const float*)d_in[2];   // [3,1024,1]
    float4* out = (float4*)d_out;

    const int n_rows = in_sizes[0] / F_DIM;    // 16384
    const int grid   = n_rows / 8;             // 8 rows (warps) per 256-thr block

    cross_layer_kernel<<<grid, 256>>>(x, w, b, out);
}